// round 11
// baseline (speedup 1.0000x reference)
#include <cuda_runtime.h>
#include <cstdint>
#include <mma.h>
#include <math.h>

using namespace nvcuda;

#define BATCH   8
#define L_SEQ   680
#define NHEADS  24
#define HDIM    64
#define CDIM    1536
#define MROWS   (BATCH * L_SEQ)      // 5440
#define QKVN    (3 * CDIM)           // 4608

// ---------------- GEMM tiling (legacy tf32 HMMA) ---------------------------
#define GBM 256
#define GBN 128
#define GBK 32
#define NSTAGE 3
#define TLD 36
#define SROWS (GBM + GBN)
#define STAGE_F (SROWS * TLD)
#define EPLD 132
#define GEMM_THREADS 256
#define GEMM_SMEM_BYTES (NSTAGE * STAGE_F * 4)   // 165888

// ---------------- attention tiling -----------------------------------------
#define ALD 68                         // row stride (68*4=272B, mult of 16B)
#define ATHREADS 128
#define ATT_SMEM_BYTES (5 * 64 * ALD * 4)   // Qs,Ks,Vs,Ss,Os = 87040

__device__ float g_qkv[MROWS * QKVN];
__device__ float g_ao [MROWS * CDIM];
__device__ float g_bias[QKVN];
__device__ float g_xr   [MROWS * CDIM];
__device__ float g_wqkvr[QKVN * CDIM];
__device__ float g_wor  [CDIM * CDIM];

// ---------------------------------------------------------------------------
__global__ void bias_compose_kernel(const float* __restrict__ qb,
                                    const float* __restrict__ vb) {
    int n = blockIdx.x * 256 + threadIdx.x;
    if (n >= QKVN) return;
    float v = 0.f;
    if (n < CDIM)            v = qb[n];
    else if (n >= 2 * CDIM)  v = vb[n - 2 * CDIM];
    g_bias[n] = v;
}

__global__ __launch_bounds__(256) void round_tf32_kernel(
    const float* __restrict__ x, float* __restrict__ y, int n4)
{
    int i = blockIdx.x * 256 + threadIdx.x;
    if (i >= n4) return;
    float4 v = ((const float4*)x)[i];
    v.x = wmma::__float_to_tf32(v.x);
    v.y = wmma::__float_to_tf32(v.y);
    v.z = wmma::__float_to_tf32(v.z);
    v.w = wmma::__float_to_tf32(v.w);
    ((float4*)y)[i] = v;
}

// ---------------------------------------------------------------------------
__device__ __forceinline__ void cp_async16(float* smem, const float* g, bool pred) {
    unsigned int saddr = (unsigned int)__cvta_generic_to_shared(smem);
    int sz = pred ? 16 : 0;
    asm volatile("cp.async.cg.shared.global [%0], [%1], 16, %2;\n"
                 :: "r"(saddr), "l"(g), "r"(sz));
}
__device__ __forceinline__ void cp_commit() {
    asm volatile("cp.async.commit_group;\n");
}
template <int N>
__device__ __forceinline__ void cp_wait() {
    asm volatile("cp.async.wait_group %0;\n" :: "n"(N));
}

// ---------------------------------------------------------------------------
// C[m][n] = sum_k A[m][k] * Bm[n][k] + bias[n]   (tf32 HMMA) — unchanged R10
// ---------------------------------------------------------------------------
__global__ __launch_bounds__(GEMM_THREADS) void gemm_tf32_bt_bias(
    const float* __restrict__ A, const float* __restrict__ Bm,
    const float* __restrict__ bias, float* __restrict__ C,
    int M, int N, int K)
{
    extern __shared__ float sm[];

    const int tid = threadIdx.x;
    const int wid = tid >> 5;
    const int m0  = blockIdx.y * GBM;
    const int n0  = blockIdx.x * GBN;
    const int wm  = wid >> 1;
    const int wn  = wid & 1;

    wmma::fragment<wmma::accumulator, 16, 16, 8, float> acc[4][4];
    #pragma unroll
    for (int i = 0; i < 4; i++)
        #pragma unroll
        for (int j = 0; j < 4; j++)
            wmma::fill_fragment(acc[i][j], 0.0f);

    const int nk = K / GBK;

    auto load_stage = [&](int s, int kc) {
        float* base = sm + s * STAGE_F;
        #pragma unroll
        for (int r = 0; r < 12; r++) {
            int u    = tid + r * GEMM_THREADS;
            int row  = u >> 3;
            int slot = u & 7;
            float* dst = base + row * TLD + slot * 4;
            if (row < GBM) {
                cp_async16(dst, A + (size_t)(m0 + row) * K + kc + slot * 4,
                           (m0 + row) < M);
            } else {
                cp_async16(dst, Bm + (size_t)(n0 + row - GBM) * K + kc + slot * 4,
                           true);
            }
        }
    };

    load_stage(0, 0);        cp_commit();
    load_stage(1, GBK);      cp_commit();

    for (int kt = 0; kt < nk; kt++) {
        cp_wait<1>();
        __syncthreads();

        if (kt + 2 < nk) {
            load_stage((kt + 2) % NSTAGE, (kt + 2) * GBK);
            cp_commit();
        }

        const float* ab = sm + (kt % NSTAGE) * STAGE_F;
        const float* bb = ab + GBM * TLD;

        #pragma unroll
        for (int ks = 0; ks < 4; ks++) {
            wmma::fragment<wmma::matrix_a, 16, 16, 8, wmma::precision::tf32,
                           wmma::row_major> af[4];
            wmma::fragment<wmma::matrix_b, 16, 16, 8, wmma::precision::tf32,
                           wmma::col_major> bf[4];
            #pragma unroll
            for (int i = 0; i < 4; i++)
                wmma::load_matrix_sync(af[i],
                    ab + (wm * 64 + i * 16) * TLD + ks * 8, TLD);
            #pragma unroll
            for (int j = 0; j < 4; j++)
                wmma::load_matrix_sync(bf[j],
                    bb + (wn * 64 + j * 16) * TLD + ks * 8, TLD);
            #pragma unroll
            for (int i = 0; i < 4; i++)
                #pragma unroll
                for (int j = 0; j < 4; j++)
                    wmma::mma_sync(acc[i][j], af[i], bf[j], acc[i][j]);
        }
    }

    __syncthreads();
    #pragma unroll
    for (int i = 0; i < 4; i++)
        #pragma unroll
        for (int j = 0; j < 4; j++)
            wmma::store_matrix_sync(
                sm + (wm * 64 + i * 16) * EPLD + wn * 64 + j * 16,
                acc[i][j], EPLD, wmma::mem_row_major);
    __syncthreads();

    if ((m0 + tid) < M) {
        float* cp = C + (size_t)(m0 + tid) * N + n0;
        const float* ep = sm + tid * EPLD;
        const float* bp = bias + n0;
        #pragma unroll
        for (int j = 0; j < 32; j++) {
            float4 v = *(const float4*)(ep + j * 4);
            v.x += bp[j * 4 + 0]; v.y += bp[j * 4 + 1];
            v.z += bp[j * 4 + 2]; v.w += bp[j * 4 + 3];
            *(float4*)(cp + j * 4) = v;
        }
    }
}

// ---------------------------------------------------------------------------
// Flash attention, tf32 wmma for S=QK^T and PV, fp32 online softmax.
// Layouts (row-major, stride ALD): Qs[q][d], Ks[key][d], Vs[key][d],
// Ss[q][key] (S then P in-place), Os[q][d] (fp32 running O).
// 128 threads = 4 warps; warp w owns rows w*16..w*16+15 in wmma phases;
// softmax phase: thread pair (2 per row) owns row tid>>1.
// ---------------------------------------------------------------------------
__device__ __forceinline__ void att_load_rope_rm(
    float* dst, const float* __restrict__ pos,
    int b, int h, int row_base, int comp_off, int tid)
{
    for (int u = tid; u < 512; u += ATHREADS) {
        int row = u >> 3;
        int d   = (u & 7) * 4;          // [0,32)
        int lg  = row_base + row;
        float4 va = {0,0,0,0}, vb = {0,0,0,0};
        float p0 = 0.f, p1 = 0.f;
        if (lg < L_SEQ) {
            const float* src = g_qkv + (size_t)(b * L_SEQ + lg) * QKVN
                               + comp_off + h * HDIM;
            va = *(const float4*)(src + d);
            vb = *(const float4*)(src + d + 32);
            p0 = pos[(size_t)(b * L_SEQ + lg) * 2 + 0];
            p1 = pos[(size_t)(b * L_SEQ + lg) * 2 + 1];
        }
        const float* xa = (const float*)&va;
        const float* xb = (const float*)&vb;
        float* drow = dst + row * ALD;
        #pragma unroll
        for (int j = 0; j < 4; j++) {
            int fi = (d + j) & 15;
            float invf = __expf(-0.5756462732485115f * (float)fi);
            float sa, ca, sb, cb;
            __sincosf(p0 * invf, &sa, &ca);
            __sincosf(p1 * invf, &sb, &cb);
            drow[d + j]      = wmma::__float_to_tf32(xa[j] * ca - xb[j] * sa);
            drow[d + 32 + j] = wmma::__float_to_tf32(xb[j] * cb + xa[j] * sb);
        }
    }
}

__global__ __launch_bounds__(ATHREADS) void attn_wmma_kernel(
    const float* __restrict__ pos, float* __restrict__ ao)
{
    extern __shared__ float smf[];
    float* Qs = smf;                 // [64][ALD]
    float* Ks = smf + 64 * ALD;
    float* Vs = smf + 2 * 64 * ALD;
    float* Ss = smf + 3 * 64 * ALD;  // S, then P in place
    float* Os = smf + 4 * 64 * ALD;  // fp32 running O

    const int qt = blockIdx.x, h = blockIdx.y, b = blockIdx.z;
    const int tid = threadIdx.x;
    const int wid = tid >> 5;
    const int q0  = qt * 64;
    const int r   = tid >> 1;        // softmax row 0..63
    const int cb0 = (tid & 1) * 32;  // softmax column half

    att_load_rope_rm(Qs, pos, b, h, q0, 0, tid);
    // zero O (cols 0..63)
    for (int u = tid; u < 1024; u += ATHREADS)
        *(float4*)(Os + (u >> 4) * ALD + (u & 15) * 4) = make_float4(0,0,0,0);

    float m_run = -1e30f, l_run = 0.f;

    const int NT = (L_SEQ + 63) / 64;   // 11
    for (int kt = 0; kt < NT; kt++) {
        int k0 = kt * 64;
        __syncthreads();   // prev PV done (Ss/P, Vs, Ks free)

        att_load_rope_rm(Ks, pos, b, h, k0, CDIM, tid);
        for (int u = tid; u < 1024; u += ATHREADS) {
            int row = u >> 4, c4 = (u & 15) * 4;
            int lg = k0 + row;
            float4 v = {0,0,0,0};
            if (lg < L_SEQ) {
                v = *(const float4*)(g_qkv + (size_t)(b*L_SEQ + lg)*QKVN
                                     + 2*CDIM + h*HDIM + c4);
                v.x = wmma::__float_to_tf32(v.x);
                v.y = wmma::__float_to_tf32(v.y);
                v.z = wmma::__float_to_tf32(v.z);
                v.w = wmma::__float_to_tf32(v.w);
            }
            *(float4*)(Vs + row * ALD + c4) = v;
        }
        __syncthreads();   // K,V ready

        // ---- S = Q K^T (warp w: rows wid*16..+15, all 64 cols) ----
        {
            wmma::fragment<wmma::accumulator, 16, 16, 8, float> acc[4];
            #pragma unroll
            for (int c = 0; c < 4; c++) wmma::fill_fragment(acc[c], 0.0f);
            #pragma unroll
            for (int ks = 0; ks < 8; ks++) {
                wmma::fragment<wmma::matrix_a, 16, 16, 8, wmma::precision::tf32,
                               wmma::row_major> af;
                wmma::load_matrix_sync(af, Qs + (wid * 16) * ALD + ks * 8, ALD);
                #pragma unroll
                for (int c = 0; c < 4; c++) {
                    wmma::fragment<wmma::matrix_b, 16, 16, 8, wmma::precision::tf32,
                                   wmma::col_major> bf;
                    wmma::load_matrix_sync(bf, Ks + (c * 16) * ALD + ks * 8, ALD);
                    wmma::mma_sync(acc[c], af, bf, acc[c]);
                }
            }
            #pragma unroll
            for (int c = 0; c < 4; c++)
                wmma::store_matrix_sync(Ss + (wid * 16) * ALD + c * 16,
                                        acc[c], ALD, wmma::mem_row_major);
        }
        __syncthreads();   // S visible

        // ---- online softmax (2 threads per row) ----
        {
            float* srow = Ss + r * ALD + cb0;
            float s[32];
            float mx = -1e30f;
            #pragma unroll
            for (int c = 0; c < 32; c++) {
                float v = srow[c] * 0.125f;
                if (k0 + cb0 + c >= L_SEQ) v = -1e30f;
                s[c] = v;
                mx = fmaxf(mx, v);
            }
            mx = fmaxf(mx, __shfl_xor_sync(0xffffffffu, mx, 1));
            float m_new = fmaxf(m_run, mx);
            float alpha = __expf(m_run - m_new);
            float rsum = 0.f;
            #pragma unroll
            for (int c = 0; c < 32; c++) {
                float p = __expf(s[c] - m_new);
                rsum += p;
                srow[c] = wmma::__float_to_tf32(p);
            }
            rsum += __shfl_xor_sync(0xffffffffu, rsum, 1);
            l_run = l_run * alpha + rsum;
            m_run = m_new;
            // rescale O row
            float* orow = Os + r * ALD + cb0;
            #pragma unroll
            for (int c = 0; c < 32; c += 4) {
                float4 v = *(float4*)(orow + c);
                v.x *= alpha; v.y *= alpha; v.z *= alpha; v.w *= alpha;
                *(float4*)(orow + c) = v;
            }
        }
        __syncthreads();   // P + scaled O visible

        // ---- O += P V (acc loaded from / stored to Os) ----
        {
            wmma::fragment<wmma::accumulator, 16, 16, 8, float> acc[4];
            #pragma unroll
            for (int c = 0; c < 4; c++)
                wmma::load_matrix_sync(acc[c], Os + (wid * 16) * ALD + c * 16,
                                       ALD, wmma::mem_row_major);
            #pragma unroll
            for (int ks = 0; ks < 8; ks++) {
                wmma::fragment<wmma::matrix_a, 16, 16, 8, wmma::precision::tf32,
                               wmma::row_major> af;
                wmma::load_matrix_sync(af, Ss + (wid * 16) * ALD + ks * 8, ALD);
                #pragma unroll
                for (int c = 0; c < 4; c++) {
                    wmma::fragment<wmma::matrix_b, 16, 16, 8, wmma::precision::tf32,
                                   wmma::row_major> bf;
                    wmma::load_matrix_sync(bf, Vs + (ks * 8) * ALD + c * 16, ALD);
                    wmma::mma_sync(acc[c], af, bf, acc[c]);
                }
            }
            #pragma unroll
            for (int c = 0; c < 4; c++)
                wmma::store_matrix_sync(Os + (wid * 16) * ALD + c * 16,
                                        acc[c], ALD, wmma::mem_row_major);
        }
    }
    __syncthreads();

    // writeout: /l, tf32-round (GEMM2 input)
    {
        int lg = q0 + r;
        if (lg < L_SEQ) {
            float inv_l = 1.0f / l_run;
            const float* orow = Os + r * ALD + cb0;
            float* dst = ao + (size_t)(b * L_SEQ + lg) * CDIM + h * HDIM + cb0;
            #pragma unroll
            for (int c = 0; c < 32; c += 4) {
                float4 v = *(const float4*)(orow + c);
                v.x = wmma::__float_to_tf32(v.x * inv_l);
                v.y = wmma::__float_to_tf32(v.y * inv_l);
                v.z = wmma::__float_to_tf32(v.z * inv_l);
                v.w = wmma::__float_to_tf32(v.w * inv_l);
                *(float4*)(dst + c) = v;
            }
        }
    }
}

// ---------------------------------------------------------------------------
extern "C" void kernel_launch(void* const* d_in, const int* in_sizes, int n_in,
                              void* d_out, int out_size)
{
    const float* x    = (const float*)d_in[0];
    const float* pos  = (const float*)d_in[1];
    const float* wqkv = (const float*)d_in[2];
    const float* qb   = (const float*)d_in[3];
    const float* vb   = (const float*)d_in[4];
    const float* wo   = (const float*)d_in[5];
    const float* bo   = (const float*)d_in[6];
    float* out = (float*)d_out;

    float *qkv_p, *ao_p, *bias_p, *xr_p, *wqkvr_p, *wor_p;
    cudaGetSymbolAddress((void**)&qkv_p,   g_qkv);
    cudaGetSymbolAddress((void**)&ao_p,    g_ao);
    cudaGetSymbolAddress((void**)&bias_p,  g_bias);
    cudaGetSymbolAddress((void**)&xr_p,    g_xr);
    cudaGetSymbolAddress((void**)&wqkvr_p, g_wqkvr);
    cudaGetSymbolAddress((void**)&wor_p,   g_wor);

    bias_compose_kernel<<<(QKVN + 255)/256, 256>>>(qb, vb);

    {
        int n4 = (MROWS * CDIM) / 4;
        round_tf32_kernel<<<(n4 + 255)/256, 256>>>(x, xr_p, n4);
        n4 = (QKVN * CDIM) / 4;
        round_tf32_kernel<<<(n4 + 255)/256, 256>>>(wqkv, wqkvr_p, n4);
        n4 = (CDIM * CDIM) / 4;
        round_tf32_kernel<<<(n4 + 255)/256, 256>>>(wo, wor_p, n4);
    }

    cudaFuncSetAttribute(gemm_tf32_bt_bias,
                         cudaFuncAttributeMaxDynamicSharedMemorySize, GEMM_SMEM_BYTES);

    dim3 g1(QKVN / GBN, (MROWS + GBM - 1) / GBM);
    gemm_tf32_bt_bias<<<g1, GEMM_THREADS, GEMM_SMEM_BYTES>>>(
        xr_p, wqkvr_p, bias_p, qkv_p, MROWS, QKVN, CDIM);

    cudaFuncSetAttribute(attn_wmma_kernel,
                         cudaFuncAttributeMaxDynamicSharedMemorySize, ATT_SMEM_BYTES);
    attn_wmma_kernel<<<dim3((L_SEQ + 63)/64, NHEADS, BATCH), ATHREADS,
                       ATT_SMEM_BYTES>>>(pos, ao_p);

    dim3 g2(CDIM / GBN, (MROWS + GBM - 1) / GBM);
    gemm_tf32_bt_bias<<<g2, GEMM_THREADS, GEMM_SMEM_BYTES>>>(
        ao_p, wor_p, bo, out, MROWS, CDIM, CDIM);
}

// round 12
// speedup vs baseline: 1.9036x; 1.9036x over previous
#include <cuda_runtime.h>
#include <cstdint>
#include <cuda_fp16.h>
#include <mma.h>
#include <math.h>

using namespace nvcuda;

#define BATCH   8
#define L_SEQ   680
#define NHEADS  24
#define HDIM    64
#define CDIM    1536
#define MROWS   (BATCH * L_SEQ)      // 5440
#define QKVN    (3 * CDIM)           // 4608
#define SM_STRIDE 68

// ---------------- GEMM tiling (fp16 HMMA m16n16k16) ------------------------
// CTA 256x128x32, 8 warps (wm 0..3 x wn 0..1), warp tile 64x64,
// 3-stage cp.async ring, one __syncthreads per k-tile.
#define GBM 256
#define GBN 128
#define HBK 32                          // halves per k-tile
#define NSTAGE 3
#define HTLD 40                         // 32 + 8 pad (halves), 80B row
#define SROWS (GBM + GBN)               // 384 rows (A then B)
#define STAGE_H (SROWS * HTLD)          // 15360 halves / stage
#define EPLD 132
#define GEMM_THREADS 256
#define GEMM_SMEM_BYTES (NSTAGE * STAGE_H * 2)   // 92160 (epilogue 67584 fits)

__device__ float  g_qkv[MROWS * QKVN];   // qkv fp32 (GEMM1 out, attn in)
__device__ float  g_bias[QKVN];
__device__ __half g_xh   [MROWS * CDIM];
__device__ __half g_wqkvh[QKVN * CDIM];
__device__ __half g_woh  [CDIM * CDIM];
__device__ __half g_aoh  [MROWS * CDIM]; // attention out (half, GEMM2 in)

// ---------------------------------------------------------------------------
__global__ void bias_compose_kernel(const float* __restrict__ qb,
                                    const float* __restrict__ vb) {
    int n = blockIdx.x * 256 + threadIdx.x;
    if (n >= QKVN) return;
    float v = 0.f;
    if (n < CDIM)            v = qb[n];
    else if (n >= 2 * CDIM)  v = vb[n - 2 * CDIM];
    g_bias[n] = v;
}

// y = half(x), vectorized; n4 = elems/4
__global__ __launch_bounds__(256) void round_half_kernel(
    const float* __restrict__ x, __half* __restrict__ y, int n4)
{
    int i = blockIdx.x * 256 + threadIdx.x;
    if (i >= n4) return;
    float4 v = ((const float4*)x)[i];
    __half2 h0 = __floats2half2_rn(v.x, v.y);
    __half2 h1 = __floats2half2_rn(v.z, v.w);
    ((__half2*)y)[2 * i + 0] = h0;
    ((__half2*)y)[2 * i + 1] = h1;
}

// ---------------------------------------------------------------------------
__device__ __forceinline__ void cp_async16h(__half* smem, const __half* g, bool pred) {
    unsigned int saddr = (unsigned int)__cvta_generic_to_shared(smem);
    int sz = pred ? 16 : 0;
    asm volatile("cp.async.cg.shared.global [%0], [%1], 16, %2;\n"
                 :: "r"(saddr), "l"(g), "r"(sz));
}
__device__ __forceinline__ void cp_commit() {
    asm volatile("cp.async.commit_group;\n");
}
template <int N>
__device__ __forceinline__ void cp_wait() {
    asm volatile("cp.async.wait_group %0;\n" :: "n"(N));
}

// ---------------------------------------------------------------------------
// C[m][n] = sum_k A[m][k] * Bm[n][k] + bias[n]   (fp16 HMMA, fp32 accum)
// ---------------------------------------------------------------------------
__global__ __launch_bounds__(GEMM_THREADS) void gemm_fp16_bt_bias(
    const __half* __restrict__ A, const __half* __restrict__ Bm,
    const float* __restrict__ bias, float* __restrict__ C,
    int M, int N, int K)
{
    extern __shared__ __half smh[];
    float* smf = reinterpret_cast<float*>(smh);

    const int tid = threadIdx.x;
    const int wid = tid >> 5;
    const int m0  = blockIdx.y * GBM;
    const int n0  = blockIdx.x * GBN;
    const int wm  = wid >> 1;          // 0..3 : 64-row block
    const int wn  = wid & 1;           // 0..1 : 64-col block

    wmma::fragment<wmma::accumulator, 16, 16, 16, float> acc[4][4];
    #pragma unroll
    for (int i = 0; i < 4; i++)
        #pragma unroll
        for (int j = 0; j < 4; j++)
            wmma::fill_fragment(acc[i][j], 0.0f);

    const int nk = K / HBK;            // 48

    // stage loader: rows 0..255 = A, 256..383 = B; 32 halves per row,
    // 1536 16B-chunks total, 6 per thread; each r-block row-uniform A/B.
    auto load_stage = [&](int s, int kc) {
        __half* base = smh + s * STAGE_H;
        #pragma unroll
        for (int r = 0; r < 6; r++) {
            int u    = tid + r * GEMM_THREADS;   // 0..1535
            int row  = u >> 2;
            int slot = u & 3;                    // 8-half chunk
            __half* dst = base + row * HTLD + slot * 8;
            if (row < GBM) {
                cp_async16h(dst, A + (size_t)(m0 + row) * K + kc + slot * 8,
                            (m0 + row) < M);
            } else {
                cp_async16h(dst, Bm + (size_t)(n0 + row - GBM) * K + kc + slot * 8,
                            true);
            }
        }
    };

    load_stage(0, 0);        cp_commit();
    load_stage(1, HBK);      cp_commit();

    for (int kt = 0; kt < nk; kt++) {
        cp_wait<1>();
        __syncthreads();

        if (kt + 2 < nk) {
            load_stage((kt + 2) % NSTAGE, (kt + 2) * HBK);
            cp_commit();
        }

        const __half* ab = smh + (kt % NSTAGE) * STAGE_H;
        const __half* bb = ab + GBM * HTLD;

        #pragma unroll
        for (int ks = 0; ks < 2; ks++) {
            wmma::fragment<wmma::matrix_a, 16, 16, 16, half,
                           wmma::row_major> af[4];
            wmma::fragment<wmma::matrix_b, 16, 16, 16, half,
                           wmma::col_major> bf[4];
            #pragma unroll
            for (int i = 0; i < 4; i++)
                wmma::load_matrix_sync(af[i],
                    ab + (wm * 64 + i * 16) * HTLD + ks * 16, HTLD);
            #pragma unroll
            for (int j = 0; j < 4; j++)
                wmma::load_matrix_sync(bf[j],
                    bb + (wn * 64 + j * 16) * HTLD + ks * 16, HTLD);
            #pragma unroll
            for (int i = 0; i < 4; i++)
                #pragma unroll
                for (int j = 0; j < 4; j++)
                    wmma::mma_sync(acc[i][j], af[i], bf[j], acc[i][j]);
        }
    }

    // epilogue: two 128-row passes through smem (fp32 view), bias, write
    #pragma unroll
    for (int pass = 0; pass < 2; pass++) {
        __syncthreads();
        if ((wm >> 1) == pass) {
            #pragma unroll
            for (int i = 0; i < 4; i++)
                #pragma unroll
                for (int j = 0; j < 4; j++)
                    wmma::store_matrix_sync(
                        smf + ((wm & 1) * 64 + i * 16) * EPLD + wn * 64 + j * 16,
                        acc[i][j], EPLD, wmma::mem_row_major);
        }
        __syncthreads();
        {
            int r = tid >> 1;                  // 0..127
            int cseg = (tid & 1) * 64;
            int m = m0 + pass * 128 + r;
            if (m < M) {
                float* cp = C + (size_t)m * N + n0 + cseg;
                const float* ep = smf + r * EPLD + cseg;
                const float* bp = bias + n0 + cseg;
                #pragma unroll
                for (int j = 0; j < 16; j++) {
                    float4 v = *(const float4*)(ep + j * 4);
                    v.x += bp[j * 4 + 0]; v.y += bp[j * 4 + 1];
                    v.z += bp[j * 4 + 2]; v.w += bp[j * 4 + 3];
                    *(float4*)(cp + j * 4) = v;
                }
            }
        }
    }
}

// ---------------------------------------------------------------------------
// Flash attention with RoPE on-the-fly (fp32 FFMA — R10 version),
// output written as half for the fp16 GEMM2.
// ---------------------------------------------------------------------------
__device__ __forceinline__ void load_rope_tile(
    float (*dstT)[SM_STRIDE], const float* __restrict__ pos,
    int b, int h, int row_base, int comp_off, int tid)
{
    for (int u = tid; u < 512; u += 256) {
        int row = u >> 3;
        int d   = (u & 7) * 4;          // d in [0,32)
        int lg  = row_base + row;
        float4 va = {0,0,0,0}, vb = {0,0,0,0};
        float p0 = 0.f, p1 = 0.f;
        if (lg < L_SEQ) {
            const float* src = g_qkv + (size_t)(b * L_SEQ + lg) * QKVN
                               + comp_off + h * HDIM;
            va = *(const float4*)(src + d);
            vb = *(const float4*)(src + d + 32);
            p0 = pos[(size_t)(b * L_SEQ + lg) * 2 + 0];
            p1 = pos[(size_t)(b * L_SEQ + lg) * 2 + 1];
        }
        const float* xa = (const float*)&va;
        const float* xb = (const float*)&vb;
        #pragma unroll
        for (int j = 0; j < 4; j++) {
            int fi = (d + j) & 15;
            float invf = __expf(-0.5756462732485115f * (float)fi); // 10000^(-fi/16)
            float sa, ca, sb, cb;
            __sincosf(p0 * invf, &sa, &ca);
            __sincosf(p1 * invf, &sb, &cb);
            dstT[d + j][row]      = xa[j] * ca - xb[j] * sa;
            dstT[d + 32 + j][row] = xb[j] * cb + xa[j] * sb;
        }
    }
}

__global__ __launch_bounds__(256) void attn_kernel(
    const float* __restrict__ pos, __half* __restrict__ aoh)
{
    extern __shared__ float smfa[];
    float (*QsT)[SM_STRIDE] = (float(*)[SM_STRIDE])(smfa);
    float (*KsT)[SM_STRIDE] = (float(*)[SM_STRIDE])(smfa + 64*SM_STRIDE);
    float (*Vs )[SM_STRIDE] = (float(*)[SM_STRIDE])(smfa + 2*64*SM_STRIDE);
    float (*PsT)[SM_STRIDE] = (float(*)[SM_STRIDE])(smfa + 3*64*SM_STRIDE);

    int qt = blockIdx.x, h = blockIdx.y, b = blockIdx.z;
    int tid = threadIdx.x;
    int ty = tid >> 4, tx = tid & 15;
    int q0 = qt * 64;

    load_rope_tile(QsT, pos, b, h, q0, 0, tid);

    float O[4][4] = {};
    float mrun[4], lrun[4];
    #pragma unroll
    for (int i = 0; i < 4; i++) { mrun[i] = -1e30f; lrun[i] = 0.f; }

    const int NT = (L_SEQ + 63) / 64;   // 11
    for (int kt = 0; kt < NT; kt++) {
        int k0 = kt * 64;
        __syncthreads();

        load_rope_tile(KsT, pos, b, h, k0, CDIM, tid);
        for (int u = tid; u < 1024; u += 256) {
            int row = u >> 4, c4 = (u & 15) << 2;
            int lg = k0 + row;
            float4 v = {0,0,0,0};
            if (lg < L_SEQ)
                v = *(const float4*)(g_qkv + (size_t)(b*L_SEQ + lg)*QKVN
                                     + 2*CDIM + h*HDIM + c4);
            *(float4*)&Vs[row][c4] = v;
        }
        __syncthreads();

        float sacc[4][4] = {};
        #pragma unroll 8
        for (int d = 0; d < 64; d++) {
            float4 a  = *(const float4*)&QsT[d][ty*4];
            float4 bq = *(const float4*)&KsT[d][tx*4];
            float av[4] = {a.x, a.y, a.z, a.w};
            float bv[4] = {bq.x, bq.y, bq.z, bq.w};
            #pragma unroll
            for (int i = 0; i < 4; i++)
                #pragma unroll
                for (int j = 0; j < 4; j++)
                    sacc[i][j] = fmaf(av[i], bv[j], sacc[i][j]);
        }
        #pragma unroll
        for (int i = 0; i < 4; i++)
            #pragma unroll
            for (int j = 0; j < 4; j++) {
                float s = sacc[i][j] * 0.125f;
                if (k0 + tx*4 + j >= L_SEQ) s = -1e30f;
                sacc[i][j] = s;
            }

        #pragma unroll
        for (int i = 0; i < 4; i++) {
            float mx = fmaxf(fmaxf(sacc[i][0], sacc[i][1]),
                             fmaxf(sacc[i][2], sacc[i][3]));
            #pragma unroll
            for (int off = 8; off >= 1; off >>= 1)
                mx = fmaxf(mx, __shfl_xor_sync(0xffffffffu, mx, off, 16));
            float m_new = fmaxf(mrun[i], mx);
            float alpha = __expf(mrun[i] - m_new);
            float rsum = 0.f;
            #pragma unroll
            for (int j = 0; j < 4; j++) {
                float p = __expf(sacc[i][j] - m_new);
                sacc[i][j] = p;
                rsum += p;
            }
            #pragma unroll
            for (int off = 8; off >= 1; off >>= 1)
                rsum += __shfl_xor_sync(0xffffffffu, rsum, off, 16);
            lrun[i] = lrun[i] * alpha + rsum;
            mrun[i] = m_new;
            #pragma unroll
            for (int j = 0; j < 4; j++) O[i][j] *= alpha;
            #pragma unroll
            for (int j = 0; j < 4; j++) PsT[tx*4 + j][ty*4 + i] = sacc[i][j];
        }
        __syncthreads();

        #pragma unroll 8
        for (int j = 0; j < 64; j++) {
            float4 a  = *(const float4*)&PsT[j][ty*4];
            float4 v4 = *(const float4*)&Vs[j][tx*4];
            float av[4] = {a.x, a.y, a.z, a.w};
            float vv[4] = {v4.x, v4.y, v4.z, v4.w};
            #pragma unroll
            for (int i = 0; i < 4; i++)
                #pragma unroll
                for (int jj = 0; jj < 4; jj++)
                    O[i][jj] = fmaf(av[i], vv[jj], O[i][jj]);
        }
    }

    #pragma unroll
    for (int i = 0; i < 4; i++) {
        int lg = q0 + ty*4 + i;
        if (lg < L_SEQ) {
            float inv_l = 1.0f / lrun[i];
            __half2 h0 = __floats2half2_rn(O[i][0]*inv_l, O[i][1]*inv_l);
            __half2 h1 = __floats2half2_rn(O[i][2]*inv_l, O[i][3]*inv_l);
            __half2* dst = (__half2*)(aoh + (size_t)(b*L_SEQ + lg)*CDIM
                                      + h*HDIM + tx*4);
            dst[0] = h0;
            dst[1] = h1;
        }
    }
}

// ---------------------------------------------------------------------------
extern "C" void kernel_launch(void* const* d_in, const int* in_sizes, int n_in,
                              void* d_out, int out_size)
{
    const float* x    = (const float*)d_in[0];
    const float* pos  = (const float*)d_in[1];
    const float* wqkv = (const float*)d_in[2];
    const float* qb   = (const float*)d_in[3];
    const float* vb   = (const float*)d_in[4];
    const float* wo   = (const float*)d_in[5];
    const float* bo   = (const float*)d_in[6];
    float* out = (float*)d_out;

    float *qkv_p, *bias_p;
    __half *xh_p, *wqkvh_p, *woh_p, *aoh_p;
    cudaGetSymbolAddress((void**)&qkv_p,   g_qkv);
    cudaGetSymbolAddress((void**)&bias_p,  g_bias);
    cudaGetSymbolAddress((void**)&xh_p,    g_xh);
    cudaGetSymbolAddress((void**)&wqkvh_p, g_wqkvh);
    cudaGetSymbolAddress((void**)&woh_p,   g_woh);
    cudaGetSymbolAddress((void**)&aoh_p,   g_aoh);

    bias_compose_kernel<<<(QKVN + 255)/256, 256>>>(qb, vb);

    // pre-convert operands to fp16
    {
        int n4 = (MROWS * CDIM) / 4;
        round_half_kernel<<<(n4 + 255)/256, 256>>>(x, xh_p, n4);
        n4 = (QKVN * CDIM) / 4;
        round_half_kernel<<<(n4 + 255)/256, 256>>>(wqkv, wqkvh_p, n4);
        n4 = (CDIM * CDIM) / 4;
        round_half_kernel<<<(n4 + 255)/256, 256>>>(wo, woh_p, n4);
    }

    cudaFuncSetAttribute(gemm_fp16_bt_bias,
                         cudaFuncAttributeMaxDynamicSharedMemorySize, GEMM_SMEM_BYTES);

    dim3 g1(QKVN / GBN, (MROWS + GBM - 1) / GBM);
    gemm_fp16_bt_bias<<<g1, GEMM_THREADS, GEMM_SMEM_BYTES>>>(
        xh_p, wqkvh_p, bias_p, qkv_p, MROWS, QKVN, CDIM);

    int smem_attn = 4 * 64 * SM_STRIDE * (int)sizeof(float);   // 69632
    cudaFuncSetAttribute(attn_kernel,
                         cudaFuncAttributeMaxDynamicSharedMemorySize, smem_attn);
    attn_kernel<<<dim3((L_SEQ + 63)/64, NHEADS, BATCH), 256, smem_attn>>>(pos, aoh_p);

    dim3 g2(CDIM / GBN, (MROWS + GBM - 1) / GBM);
    gemm_fp16_bt_bias<<<g2, GEMM_THREADS, GEMM_SMEM_BYTES>>>(
        aoh_p, woh_p, bo, out, MROWS, CDIM, CDIM);
}

// round 13
// speedup vs baseline: 2.8185x; 1.4806x over previous
#include <cuda_runtime.h>
#include <cstdint>
#include <cuda_fp16.h>
#include <mma.h>
#include <math.h>

using namespace nvcuda;

#define BATCH   8
#define L_SEQ   680
#define NHEADS  24
#define HDIM    64
#define CDIM    1536
#define MROWS   (BATCH * L_SEQ)      // 5440
#define QKVN    (3 * CDIM)           // 4608

// ---------------- GEMM tiling (fp16 HMMA m16n16k16) ------------------------
#define GBM 256
#define GBN 128
#define HBK 32
#define NSTAGE 3
#define HTLD 40
#define SROWS (GBM + GBN)
#define STAGE_H (SROWS * HTLD)
#define EPLD 132
#define GEMM_THREADS 256
#define GEMM_SMEM_BYTES (NSTAGE * STAGE_H * 2)   // 92160

// ---------------- attention tiling (fp16 HMMA flash) -----------------------
#define AQ 128                       // q rows per CTA
#define AK 64                        // keys per tile
#define QLD 72                       // half leading dim (mult of 8)
#define SLD 68                       // float leading dim (mult of 4)
#define ATHREADS 256
// smem byte offsets
#define OFF_Q   0
#define OFF_K   (OFF_Q + AQ * QLD * 2)            // 18432
#define OFF_V   (OFF_K + 2 * AK * QLD * 2)        // +18432 = 36864
#define OFF_S   (OFF_V + 2 * AK * QLD * 2)        // +18432 = 55296
#define OFF_P   (OFF_S + AQ * SLD * 4)            // +34816 = 90112
#define OFF_O   (OFF_P + AQ * QLD * 2)            // +18432 = 108544
#define ATT_SMEM_BYTES (OFF_O + AQ * SLD * 4)     // 143360

__device__ float  g_bias[QKVN];
__device__ __half g_xh   [MROWS * CDIM];
__device__ __half g_wqkvh[QKVN * CDIM];
__device__ __half g_woh  [CDIM * CDIM];
__device__ __half g_qkvh [MROWS * QKVN];   // half qkv (GEMM1 out, roped in place)
__device__ __half g_aoh  [MROWS * CDIM];   // attention out (half, GEMM2 in)

// ---------------------------------------------------------------------------
__global__ void bias_compose_kernel(const float* __restrict__ qb,
                                    const float* __restrict__ vb) {
    int n = blockIdx.x * 256 + threadIdx.x;
    if (n >= QKVN) return;
    float v = 0.f;
    if (n < CDIM)            v = qb[n];
    else if (n >= 2 * CDIM)  v = vb[n - 2 * CDIM];
    g_bias[n] = v;
}

__global__ __launch_bounds__(256) void round_half_kernel(
    const float* __restrict__ x, __half* __restrict__ y, int n4)
{
    int i = blockIdx.x * 256 + threadIdx.x;
    if (i >= n4) return;
    float4 v = ((const float4*)x)[i];
    ((__half2*)y)[2 * i + 0] = __floats2half2_rn(v.x, v.y);
    ((__half2*)y)[2 * i + 1] = __floats2half2_rn(v.z, v.w);
}

// ---------------------------------------------------------------------------
__device__ __forceinline__ void cp_async16h(__half* smem, const __half* g, bool pred) {
    unsigned int saddr = (unsigned int)__cvta_generic_to_shared(smem);
    int sz = pred ? 16 : 0;
    asm volatile("cp.async.cg.shared.global [%0], [%1], 16, %2;\n"
                 :: "r"(saddr), "l"(g), "r"(sz));
}
__device__ __forceinline__ void cp_commit() {
    asm volatile("cp.async.commit_group;\n");
}
template <int N>
__device__ __forceinline__ void cp_wait() {
    asm volatile("cp.async.wait_group %0;\n" :: "n"(N));
}

// ---------------------------------------------------------------------------
// C[m][n] = sum_k A[m][k]*Bm[n][k] + bias[n] (fp16 HMMA, fp32 accum)
// Output: Cf (fp32) or Ch (half) — exactly one non-null.
// ---------------------------------------------------------------------------
__global__ __launch_bounds__(GEMM_THREADS) void gemm_fp16_bt_bias(
    const __half* __restrict__ A, const __half* __restrict__ Bm,
    const float* __restrict__ bias, float* __restrict__ Cf,
    __half* __restrict__ Ch, int M, int N, int K)
{
    extern __shared__ __half smh[];
    float* smf = reinterpret_cast<float*>(smh);

    const int tid = threadIdx.x;
    const int wid = tid >> 5;
    const int m0  = blockIdx.y * GBM;
    const int n0  = blockIdx.x * GBN;
    const int wm  = wid >> 1;
    const int wn  = wid & 1;

    wmma::fragment<wmma::accumulator, 16, 16, 16, float> acc[4][4];
    #pragma unroll
    for (int i = 0; i < 4; i++)
        #pragma unroll
        for (int j = 0; j < 4; j++)
            wmma::fill_fragment(acc[i][j], 0.0f);

    const int nk = K / HBK;

    auto load_stage = [&](int s, int kc) {
        __half* base = smh + s * STAGE_H;
        #pragma unroll
        for (int r = 0; r < 6; r++) {
            int u    = tid + r * GEMM_THREADS;
            int row  = u >> 2;
            int slot = u & 3;
            __half* dst = base + row * HTLD + slot * 8;
            if (row < GBM) {
                cp_async16h(dst, A + (size_t)(m0 + row) * K + kc + slot * 8,
                            (m0 + row) < M);
            } else {
                cp_async16h(dst, Bm + (size_t)(n0 + row - GBM) * K + kc + slot * 8,
                            true);
            }
        }
    };

    load_stage(0, 0);        cp_commit();
    load_stage(1, HBK);      cp_commit();

    for (int kt = 0; kt < nk; kt++) {
        cp_wait<1>();
        __syncthreads();

        if (kt + 2 < nk) {
            load_stage((kt + 2) % NSTAGE, (kt + 2) * HBK);
            cp_commit();
        }

        const __half* ab = smh + (kt % NSTAGE) * STAGE_H;
        const __half* bb = ab + GBM * HTLD;

        #pragma unroll
        for (int ks = 0; ks < 2; ks++) {
            wmma::fragment<wmma::matrix_a, 16, 16, 16, half,
                           wmma::row_major> af[4];
            wmma::fragment<wmma::matrix_b, 16, 16, 16, half,
                           wmma::col_major> bf[4];
            #pragma unroll
            for (int i = 0; i < 4; i++)
                wmma::load_matrix_sync(af[i],
                    ab + (wm * 64 + i * 16) * HTLD + ks * 16, HTLD);
            #pragma unroll
            for (int j = 0; j < 4; j++)
                wmma::load_matrix_sync(bf[j],
                    bb + (wn * 64 + j * 16) * HTLD + ks * 16, HTLD);
            #pragma unroll
            for (int i = 0; i < 4; i++)
                #pragma unroll
                for (int j = 0; j < 4; j++)
                    wmma::mma_sync(acc[i][j], af[i], bf[j], acc[i][j]);
        }
    }

    // epilogue: two 128-row passes through smem, bias, write (fp32 or half)
    #pragma unroll
    for (int pass = 0; pass < 2; pass++) {
        __syncthreads();
        if ((wm >> 1) == pass) {
            #pragma unroll
            for (int i = 0; i < 4; i++)
                #pragma unroll
                for (int j = 0; j < 4; j++)
                    wmma::store_matrix_sync(
                        smf + ((wm & 1) * 64 + i * 16) * EPLD + wn * 64 + j * 16,
                        acc[i][j], EPLD, wmma::mem_row_major);
        }
        __syncthreads();
        {
            int r = tid >> 1;
            int cseg = (tid & 1) * 64;
            int m = m0 + pass * 128 + r;
            if (m < M) {
                const float* ep = smf + r * EPLD + cseg;
                const float* bp = bias + n0 + cseg;
                if (Cf) {
                    float* cp = Cf + (size_t)m * N + n0 + cseg;
                    #pragma unroll
                    for (int j = 0; j < 16; j++) {
                        float4 v = *(const float4*)(ep + j * 4);
                        v.x += bp[j * 4 + 0]; v.y += bp[j * 4 + 1];
                        v.z += bp[j * 4 + 2]; v.w += bp[j * 4 + 3];
                        *(float4*)(cp + j * 4) = v;
                    }
                } else {
                    __half2* cp = (__half2*)(Ch + (size_t)m * N + n0 + cseg);
                    #pragma unroll
                    for (int j = 0; j < 16; j++) {
                        float4 v = *(const float4*)(ep + j * 4);
                        cp[2 * j + 0] = __floats2half2_rn(v.x + bp[j*4+0],
                                                          v.y + bp[j*4+1]);
                        cp[2 * j + 1] = __floats2half2_rn(v.z + bp[j*4+2],
                                                          v.w + bp[j*4+3]);
                    }
                }
            }
        }
    }
}

// ---------------------------------------------------------------------------
// RoPE in place over q and k components of g_qkvh (half in/out, fp32 math).
// dims 0..31 use p0, 32..63 use p1, freq index = d & 15, pair (d, d+32).
// ---------------------------------------------------------------------------
__global__ __launch_bounds__(256) void rope_kernel(
    const float* __restrict__ pos, __half* __restrict__ qkvh)
{
    int u = blockIdx.x * 256 + threadIdx.x;
    const int total = MROWS * 2 * NHEADS * 8;
    if (u >= total) return;
    int quad = u & 7;  u >>= 3;
    int h    = u % NHEADS; u /= NHEADS;
    int comp = u & 1;  int row = u >> 1;          // 0..MROWS-1
    int d = quad * 4;                              // 0,4,...,28

    __half* base = qkvh + (size_t)row * QKVN + comp * CDIM + h * HDIM;
    float p0 = pos[(size_t)row * 2 + 0];
    float p1 = pos[(size_t)row * 2 + 1];

    __half2 lo01 = *(__half2*)(base + d);
    __half2 lo23 = *(__half2*)(base + d + 2);
    __half2 hi01 = *(__half2*)(base + d + 32);
    __half2 hi23 = *(__half2*)(base + d + 32 + 2);
    float lo[4] = { __half2float(lo01.x), __half2float(lo01.y),
                    __half2float(lo23.x), __half2float(lo23.y) };
    float hi[4] = { __half2float(hi01.x), __half2float(hi01.y),
                    __half2float(hi23.x), __half2float(hi23.y) };
    float nlo[4], nhi[4];
    #pragma unroll
    for (int j = 0; j < 4; j++) {
        int fi = (d + j) & 15;
        float invf = __expf(-0.5756462732485115f * (float)fi);
        float sa, ca, sb, cb;
        __sincosf(p0 * invf, &sa, &ca);
        __sincosf(p1 * invf, &sb, &cb);
        nlo[j] = lo[j] * ca - hi[j] * sa;
        nhi[j] = hi[j] * cb + lo[j] * sb;
    }
    *(__half2*)(base + d)          = __floats2half2_rn(nlo[0], nlo[1]);
    *(__half2*)(base + d + 2)      = __floats2half2_rn(nlo[2], nlo[3]);
    *(__half2*)(base + d + 32)     = __floats2half2_rn(nhi[0], nhi[1]);
    *(__half2*)(base + d + 32 + 2) = __floats2half2_rn(nhi[2], nhi[3]);
}

// ---------------------------------------------------------------------------
// Flash attention: fp16 wmma for S=QK^T and PV, fp32 softmax + O.
// 128 q-rows per CTA, 8 warps (warp = 16 q-rows), K/V double-buffered cp.async.
// ---------------------------------------------------------------------------
__global__ __launch_bounds__(ATHREADS) void attn_fp16_kernel(
    const __half* __restrict__ qkvh, __half* __restrict__ aoh)
{
    extern __shared__ char smb[];
    __half* Qs = (__half*)(smb + OFF_Q);
    __half* Ks = (__half*)(smb + OFF_K);     // [2][AK][QLD]
    __half* Vs = (__half*)(smb + OFF_V);     // [2][AK][QLD]
    float*  Ss = (float* )(smb + OFF_S);     // [AQ][SLD]
    __half* Ps = (__half*)(smb + OFF_P);     // [AQ][QLD]
    float*  Os = (float* )(smb + OFF_O);     // [AQ][SLD]

    const int qt = blockIdx.x, h = blockIdx.y, b = blockIdx.z;
    const int tid = threadIdx.x;
    const int wid = tid >> 5;
    const int q0  = qt * AQ;
    const int r   = tid >> 1;        // softmax row 0..127
    const int cb0 = (tid & 1) * 32;  // softmax column half

    // load Q tile (roped, half): 1024 16B-chunks, 4/thread
    #pragma unroll
    for (int c = 0; c < 4; c++) {
        int u = tid + c * ATHREADS;
        int row = u >> 3, slot = u & 7;
        int lg = q0 + row;
        cp_async16h(Qs + row * QLD + slot * 8,
                    qkvh + (size_t)(b * L_SEQ + (lg < L_SEQ ? lg : 0)) * QKVN
                         + h * HDIM + slot * 8,
                    lg < L_SEQ);
    }
    cp_commit();

    // zero O
    #pragma unroll
    for (int c = 0; c < 8; c++) {
        int u = tid + c * ATHREADS;     // 0..2047
        Os[(u >> 4) * SLD + (u & 15) * 4 + 0] = 0.f;
        Os[(u >> 4) * SLD + (u & 15) * 4 + 1] = 0.f;
        Os[(u >> 4) * SLD + (u & 15) * 4 + 2] = 0.f;
        Os[(u >> 4) * SLD + (u & 15) * 4 + 3] = 0.f;
    }

    // K/V tile loader into buffer bf
    auto load_kv = [&](int bf, int k0) {
        __half* kd = Ks + bf * AK * QLD;
        __half* vd = Vs + bf * AK * QLD;
        #pragma unroll
        for (int c = 0; c < 2; c++) {
            int u = tid + c * ATHREADS;      // 0..511
            int row = u >> 3, slot = u & 7;
            int lg = k0 + row;
            bool ok = lg < L_SEQ;
            size_t gro = (size_t)(b * L_SEQ + (ok ? lg : 0)) * QKVN + h * HDIM
                         + slot * 8;
            cp_async16h(kd + row * QLD + slot * 8, qkvh + gro + CDIM, ok);
            cp_async16h(vd + row * QLD + slot * 8, qkvh + gro + 2 * CDIM, ok);
        }
    };

    load_kv(0, 0);
    cp_commit();

    float m_run = -1e30f, l_run = 0.f;
    const int NT = (L_SEQ + AK - 1) / AK;   // 11

    for (int kt = 0; kt < NT; kt++) {
        int k0 = kt * AK;
        cp_wait<0>();
        __syncthreads();          // data ready + prev PV done (buffers free)

        if (kt + 1 < NT) {
            load_kv((kt + 1) & 1, k0 + AK);
            cp_commit();
        }

        const __half* kb = Ks + (kt & 1) * AK * QLD;
        const __half* vb = Vs + (kt & 1) * AK * QLD;

        // ---- S = Q K^T : warp rows wid*16, 64 key cols ----
        {
            const int wr0 = wid * 16;
            wmma::fragment<wmma::accumulator, 16, 16, 16, float> acc[4];
            #pragma unroll
            for (int c = 0; c < 4; c++) wmma::fill_fragment(acc[c], 0.0f);
            #pragma unroll
            for (int ks = 0; ks < 4; ks++) {
                wmma::fragment<wmma::matrix_a, 16, 16, 16, half,
                               wmma::row_major> af;
                wmma::load_matrix_sync(af, Qs + wr0 * QLD + ks * 16, QLD);
                #pragma unroll
                for (int c = 0; c < 4; c++) {
                    wmma::fragment<wmma::matrix_b, 16, 16, 16, half,
                                   wmma::col_major> bf;
                    wmma::load_matrix_sync(bf, kb + (c * 16) * QLD + ks * 16, QLD);
                    wmma::mma_sync(acc[c], af, bf, acc[c]);
                }
            }
            #pragma unroll
            for (int c = 0; c < 4; c++)
                wmma::store_matrix_sync(Ss + wr0 * SLD + c * 16, acc[c],
                                        SLD, wmma::mem_row_major);
        }
        __syncthreads();

        // ---- online softmax (2 threads per row) ----
        {
            float* srow = Ss + r * SLD + cb0;
            float s[32];
            float mx = -1e30f;
            #pragma unroll
            for (int c = 0; c < 32; c++) {
                float v = srow[c] * 0.125f;
                if (k0 + cb0 + c >= L_SEQ) v = -1e30f;
                s[c] = v;
                mx = fmaxf(mx, v);
            }
            mx = fmaxf(mx, __shfl_xor_sync(0xffffffffu, mx, 1));
            float m_new = fmaxf(m_run, mx);
            float alpha = __expf(m_run - m_new);
            float rsum = 0.f;
            __half2* prow = (__half2*)(Ps + r * QLD + cb0);
            #pragma unroll
            for (int c = 0; c < 32; c += 2) {
                float p0v = __expf(s[c]     - m_new);
                float p1v = __expf(s[c + 1] - m_new);
                rsum += p0v + p1v;
                prow[c >> 1] = __floats2half2_rn(p0v, p1v);
            }
            rsum += __shfl_xor_sync(0xffffffffu, rsum, 1);
            l_run = l_run * alpha + rsum;
            m_run = m_new;
            float* orow = Os + r * SLD + cb0;
            #pragma unroll
            for (int c = 0; c < 32; c += 4) {
                float4 v = *(float4*)(orow + c);
                v.x *= alpha; v.y *= alpha; v.z *= alpha; v.w *= alpha;
                *(float4*)(orow + c) = v;
            }
        }
        __syncthreads();

        // ---- O += P V ----
        {
            const int wr0 = wid * 16;
            wmma::fragment<wmma::accumulator, 16, 16, 16, float> acc[4];
            #pragma unroll
            for (int c = 0; c < 4; c++)
                wmma::load_matrix_sync(acc[c], Os + wr0 * SLD + c * 16,
                                       SLD, wmma::mem_row_major);
            #pragma unroll
            for (int ks = 0; ks < 4; ks++) {
                wmma::fragment<wmma::matrix_a, 16, 16, 16, half,
                               wmma::row_major> af;
                wmma::load_matrix_sync(af, Ps + wr0 * QLD + ks * 16, QLD);
                #pragma unroll
                for (int c = 0; c < 4; c++) {
                    wmma::fragment<wmma::matrix_b, 16, 16, 16, half,
                                   wmma::row_major> bf;
                    wmma::load_matrix_sync(bf, vb + (ks * 16) * QLD + c * 16, QLD);
                    wmma::mma_sync(acc[c], af, bf, acc[c]);
                }
            }
            #pragma unroll
            for (int c = 0; c < 4; c++)
                wmma::store_matrix_sync(Os + wr0 * SLD + c * 16, acc[c],
                                        SLD, wmma::mem_row_major);
        }
    }
    __syncthreads();

    // writeout: /l, half
    {
        int lg = q0 + r;
        if (lg < L_SEQ) {
            float inv_l = 1.0f / l_run;
            const float* orow = Os + r * SLD + cb0;
            __half2* dst = (__half2*)(aoh + (size_t)(b * L_SEQ + lg) * CDIM
                                      + h * HDIM + cb0);
            #pragma unroll
            for (int c = 0; c < 32; c += 2)
                dst[c >> 1] = __floats2half2_rn(orow[c] * inv_l,
                                                orow[c + 1] * inv_l);
        }
    }
}

// ---------------------------------------------------------------------------
extern "C" void kernel_launch(void* const* d_in, const int* in_sizes, int n_in,
                              void* d_out, int out_size)
{
    const float* x    = (const float*)d_in[0];
    const float* pos  = (const float*)d_in[1];
    const float* wqkv = (const float*)d_in[2];
    const float* qb   = (const float*)d_in[3];
    const float* vb   = (const float*)d_in[4];
    const float* wo   = (const float*)d_in[5];
    const float* bo   = (const float*)d_in[6];
    float* out = (float*)d_out;

    float *bias_p;
    __half *xh_p, *wqkvh_p, *woh_p, *qkvh_p, *aoh_p;
    cudaGetSymbolAddress((void**)&bias_p,  g_bias);
    cudaGetSymbolAddress((void**)&xh_p,    g_xh);
    cudaGetSymbolAddress((void**)&wqkvh_p, g_wqkvh);
    cudaGetSymbolAddress((void**)&woh_p,   g_woh);
    cudaGetSymbolAddress((void**)&qkvh_p,  g_qkvh);
    cudaGetSymbolAddress((void**)&aoh_p,   g_aoh);

    bias_compose_kernel<<<(QKVN + 255)/256, 256>>>(qb, vb);

    {
        int n4 = (MROWS * CDIM) / 4;
        round_half_kernel<<<(n4 + 255)/256, 256>>>(x, xh_p, n4);
        n4 = (QKVN * CDIM) / 4;
        round_half_kernel<<<(n4 + 255)/256, 256>>>(wqkv, wqkvh_p, n4);
        n4 = (CDIM * CDIM) / 4;
        round_half_kernel<<<(n4 + 255)/256, 256>>>(wo, woh_p, n4);
    }

    cudaFuncSetAttribute(gemm_fp16_bt_bias,
                         cudaFuncAttributeMaxDynamicSharedMemorySize, GEMM_SMEM_BYTES);

    // GEMM1: qkv (half out)
    dim3 g1(QKVN / GBN, (MROWS + GBM - 1) / GBM);
    gemm_fp16_bt_bias<<<g1, GEMM_THREADS, GEMM_SMEM_BYTES>>>(
        xh_p, wqkvh_p, bias_p, nullptr, qkvh_p, MROWS, QKVN, CDIM);

    // RoPE in place on q,k
    {
        int total = MROWS * 2 * NHEADS * 8;
        rope_kernel<<<(total + 255)/256, 256>>>(pos, qkvh_p);
    }

    // attention
    cudaFuncSetAttribute(attn_fp16_kernel,
                         cudaFuncAttributeMaxDynamicSharedMemorySize, ATT_SMEM_BYTES);
    attn_fp16_kernel<<<dim3((L_SEQ + AQ - 1)/AQ, NHEADS, BATCH), ATHREADS,
                       ATT_SMEM_BYTES>>>(qkvh_p, aoh_p);

    // GEMM2: out (fp32)
    dim3 g2(CDIM / GBN, (MROWS + GBM - 1) / GBM);
    gemm_fp16_bt_bias<<<g2, GEMM_THREADS, GEMM_SMEM_BYTES>>>(
        aoh_p, woh_p, bo, out, nullptr, MROWS, CDIM, CDIM);
}